// round 9
// baseline (speedup 1.0000x reference)
#include <cuda_runtime.h>

#define NRES    4096
#define NPAIRS  500000

#define NTHREADS     1024
#define HB_BLOCKS    16                   // 16*1024 = 16384 = 4*4096 hb items, 1/thread
#define CL_BLOCKS    16
#define BD_BLOCKS    1
#define SP_BLOCKS    (HB_BLOCKS + CL_BLOCKS + BD_BLOCKS)   // specials first: 33

#define CT_ROWS      16                   // rows per contact block (256 KB contiguous)
#define CT_BLOCKS    (NRES / CT_ROWS)     // 256
#define NB_TOTAL     (SP_BLOCKS + CT_BLOCKS)    // 289  (<= 148*2 = 296: one wave)

// accumulators: [0]=bond, [1]=clash, [2]=contact, [3]=hb pen sum
__device__ double g_acc[4];
__device__ unsigned int g_done;

__device__ __forceinline__ float fast_sqrt(float x) {
    float r; asm("sqrt.approx.f32 %0, %1;" : "=f"(r) : "f"(x)); return r;
}

__device__ __forceinline__ float3 ldca(const float* __restrict__ ca, int i) {
    return make_float3(__ldg(ca + 3*i), __ldg(ca + 3*i + 1), __ldg(ca + 3*i + 2));
}

__device__ __forceinline__ float3 unitv(const float* __restrict__ ca, int i) {
    float3 a = ldca(ca, i), b = ldca(ca, i + 1);
    float vx = b.x - a.x, vy = b.y - a.y, vz = b.z - a.z;
    float n = sqrtf(vx*vx + vy*vy + vz*vz) + 1e-8f;
    float inv = 1.0f / n;
    return make_float3(vx*inv, vy*inv, vz*inv);
}

__device__ __forceinline__ float3 o_coord(const float* __restrict__ ca, int i) {
    float3 u  = unitv(ca, i);
    float3 up = unitv(ca, (i > 0) ? i - 1 : 0);
    float3 cai = ldca(ca, i);
    float3 vc = make_float3(0.38f*u.x, 0.38f*u.y, 0.38f*u.z);
    float3 vn = make_float3(-0.38f*up.x, -0.38f*up.y, -0.38f*up.z);
    float px = vc.y*vn.z - vc.z*vn.y;
    float py = vc.z*vn.x - vc.x*vn.z;
    float pz = vc.x*vn.y - vc.y*vn.x;
    float pn = sqrtf(px*px + py*py + pz*pz);
    if (pn > 1e-6f) {
        float inv = 1.0f / fmaxf(pn, 1e-12f);
        px *= inv; py *= inv; pz *= inv;
    }
    return make_float3(cai.x + vc.x + 1.24f*px,
                       cai.y + vc.y + 1.24f*py,
                       cai.z + vc.z + 1.24f*pz);
}

__device__ __forceinline__ float3 n_coord(const float* __restrict__ ca, int j) {
    float3 u = unitv(ca, j - 1);
    float3 caj = ldca(ca, j);
    return make_float3(caj.x - 0.38f*u.x, caj.y - 0.38f*u.y, caj.z - 0.38f*u.z);
}

__global__ void __launch_bounds__(NTHREADS, 2)
energy_kernel(const float* __restrict__ ca, const float* __restrict__ K,
              const int2* __restrict__ pairs, float* __restrict__ out)
{
    __shared__ double sh[NTHREADS / 32];
    const int bid = blockIdx.x;
    const int tid = threadIdx.x;

    float acc = 0.0f;
    int role;

    if (bid >= SP_BLOCKS) {
        // ------- contact: one full 16KB row per block-iteration, ----------
        // ------- 16 consecutive rows = 256KB contiguous per block ---------
        role = 2;
        const int cb = bid - SP_BLOCKS;
        const int j0 = tid * 4;                   // full row coverage: 1024 thr * 4 cols

        const float4* cj4 = (const float4*)(ca + 3 * j0);  // 16B-aligned (j0 % 4 == 0)
        float4 A = __ldg(cj4 + 0);
        float4 B = __ldg(cj4 + 1);
        float4 C = __ldg(cj4 + 2);
        const float xj0 = A.x, yj0 = A.y, zj0 = A.z;
        const float xj1 = A.w, yj1 = B.x, zj1 = B.y;
        const float xj2 = B.z, yj2 = B.w, zj2 = C.x;
        const float xj3 = C.y, yj3 = C.z, zj3 = C.w;

        const int i0 = cb * CT_ROWS;
        #pragma unroll 4
        for (int i = i0; i < i0 + CT_ROWS; ++i) {
            const float xi = __ldg(ca + 3*i + 0);
            const float yi = __ldg(ca + 3*i + 1);
            const float zi = __ldg(ca + 3*i + 2);
            const float4 k = __ldg((const float4*)(K + (size_t)i * NRES + j0));

            float dx, dy, dz, q, d, t, df;

            dx = xi - xj0; dy = yi - yj0; dz = zi - zj0;
            q = fmaf(dx, dx, fmaf(dy, dy, dz * dz));
            d = fast_sqrt(fmaxf(q, 1e-12f));
            t = fmaf(-8.0f, k.x, 8.0f);
            df = d - t; acc = fmaf(df, df, acc);

            dx = xi - xj1; dy = yi - yj1; dz = zi - zj1;
            q = fmaf(dx, dx, fmaf(dy, dy, dz * dz));
            d = fast_sqrt(fmaxf(q, 1e-12f));
            t = fmaf(-8.0f, k.y, 8.0f);
            df = d - t; acc = fmaf(df, df, acc);

            dx = xi - xj2; dy = yi - yj2; dz = zi - zj2;
            q = fmaf(dx, dx, fmaf(dy, dy, dz * dz));
            d = fast_sqrt(fmaxf(q, 1e-12f));
            t = fmaf(-8.0f, k.z, 8.0f);
            df = d - t; acc = fmaf(df, df, acc);

            dx = xi - xj3; dy = yi - yj3; dz = zi - zj3;
            q = fmaf(dx, dx, fmaf(dy, dy, dz * dz));
            d = fast_sqrt(fmaxf(q, 1e-12f));
            t = fmaf(-8.0f, k.w, 8.0f);
            df = d - t; acc = fmaf(df, df, acc);
        }
    } else if (bid < HB_BLOCKS) {
        // ---------------- hydrogen bonds: 16384 items, exactly 1 per thread ----
        role = 3;
        const int idx = bid * NTHREADS + tid;         // [0, 4*NRES)
        const int off = 2 + (idx >> 12);
        const int i = idx & (NRES - 1);
        if (i < NRES - off) {
            const float3 o  = o_coord(ca, i);
            const float3 nc = n_coord(ca, i + off);
            const float dx = o.x - nc.x, dy = o.y - nc.y, dz = o.z - nc.z;
            const float d = sqrtf(dx*dx + dy*dy + dz*dz);
            if (d > 2.5f && d < 3.5f) {
                const float z = (d - 2.95f) * (1.0f / 0.3f);
                acc += expf(-z * z);   // pen; sign/weight applied at finalize
            }
        }
    } else if (bid < HB_BLOCKS + CL_BLOCKS) {
        // ---------------- clash: 500K pairs over 16 blocks -----------------
        role = 1;
        const int b = bid - HB_BLOCKS;
        for (int p = b * NTHREADS + tid; p < NPAIRS; p += CL_BLOCKS * NTHREADS) {
            const int2 pr = __ldg(pairs + p);
            const int i = pr.x, j = pr.y;
            const float dx = __ldg(ca + 3*i + 0) - __ldg(ca + 3*j + 0);
            const float dy = __ldg(ca + 3*i + 1) - __ldg(ca + 3*j + 1);
            const float dz = __ldg(ca + 3*i + 2) - __ldg(ca + 3*j + 2);
            float q = fmaf(dx, dx, fmaf(dy, dy, dz * dz));
            float d = fast_sqrt(fmaxf(q, 1e-12f));
            float r = fmaxf(3.2f - d, 0.0f);
            acc = fmaf(r, r, acc);
        }
    } else {
        // ---------------- bond: 4095 terms -----------------
        role = 0;
        for (int i = tid; i < NRES - 1; i += NTHREADS) {
            const float dx = __ldg(ca + 3*i + 3) - __ldg(ca + 3*i + 0);
            const float dy = __ldg(ca + 3*i + 4) - __ldg(ca + 3*i + 1);
            const float dz = __ldg(ca + 3*i + 5) - __ldg(ca + 3*i + 2);
            const float d = fast_sqrt(fmaf(dx, dx, fmaf(dy, dy, dz * dz)));
            const float df = d - 3.8f;
            acc = fmaf(df, df, acc);
        }
    }

    // ---------------- block reduce (f64) + single atomic ----------------
    double v = (double)acc;
    #pragma unroll
    for (int o = 16; o > 0; o >>= 1) v += __shfl_xor_sync(0xffffffffu, v, o);
    const int lane = tid & 31, w = tid >> 5;
    if (lane == 0) sh[w] = v;
    __syncthreads();

    if (tid == 0) {
        double tot = 0.0;
        #pragma unroll
        for (int i = 0; i < NTHREADS / 32; ++i) tot += sh[i];
        atomicAdd(&g_acc[role], tot);
        __threadfence();
        const unsigned int ticket = atomicAdd(&g_done, 1u);
        if (ticket == (unsigned int)(gridDim.x - 1)) {
            // last block: finalize, write output, self-reset for next graph replay
            const double bond    = atomicAdd(&g_acc[0], 0.0);
            const double clash   = atomicAdd(&g_acc[1], 0.0);
            const double contact = atomicAdd(&g_acc[2], 0.0);
            const double hb      = atomicAdd(&g_acc[3], 0.0);
            const double inv_nn  = 1.0 / ((double)NRES * (double)NRES);
            const double e = 30.0 * bond / (double)(NRES - 1)
                           + 50.0 * clash / (double)NPAIRS
                           + 5.0 * contact * inv_nn
                           - 2.0 * hb * inv_nn;       // 4 * (-0.5*sum) / n^2
            out[0] = (float)e;
            g_acc[0] = 0.0; g_acc[1] = 0.0; g_acc[2] = 0.0; g_acc[3] = 0.0;
            __threadfence();
            g_done = 0u;
        }
    }
}

extern "C" void kernel_launch(void* const* d_in, const int* in_sizes, int n_in,
                              void* d_out, int out_size) {
    const float* ca    = (const float*)d_in[0];
    const float* K     = (const float*)d_in[1];
    const int2*  pairs = (const int2*)d_in[2];
    energy_kernel<<<NB_TOTAL, NTHREADS>>>(ca, K, pairs, (float*)d_out);
}

// round 10
// speedup vs baseline: 1.8558x; 1.8558x over previous
#include <cuda_runtime.h>

#define NRES    4096
#define NPAIRS  500000

#define NTHREADS     256
#define HB_BLOCKS    64                   // 64*256 = 16384 = 4*4096 hb items, 1/thread
#define CL_BLOCKS    64
#define BD_BLOCKS    1
#define SP_BLOCKS    (HB_BLOCKS + CL_BLOCKS + BD_BLOCKS)   // specials first: 129

#define CT_JBLOCKS   4                    // 4096 cols / (256 thr * 4 cols)
#define CT_ROWS      16                   // rows per contact block
#define CT_RBLOCKS   (NRES / CT_ROWS)     // 256
#define CT_BLOCKS    (CT_JBLOCKS * CT_RBLOCKS)  // 1024
#define NB_TOTAL     (SP_BLOCKS + CT_BLOCKS)    // 1153  (< 148*8 = 1184: one wave)

// accumulators: [0]=bond, [1]=clash, [2]=contact, [3]=hb pen sum
__device__ double g_acc[4];
__device__ unsigned int g_done;

__device__ __forceinline__ float fast_sqrt(float x) {
    float r; asm("sqrt.approx.f32 %0, %1;" : "=f"(r) : "f"(x)); return r;
}

__device__ __forceinline__ float3 ldca(const float* __restrict__ ca, int i) {
    return make_float3(__ldg(ca + 3*i), __ldg(ca + 3*i + 1), __ldg(ca + 3*i + 2));
}

__device__ __forceinline__ float3 unitv(const float* __restrict__ ca, int i) {
    float3 a = ldca(ca, i), b = ldca(ca, i + 1);
    float vx = b.x - a.x, vy = b.y - a.y, vz = b.z - a.z;
    float n = sqrtf(vx*vx + vy*vy + vz*vz) + 1e-8f;
    float inv = 1.0f / n;
    return make_float3(vx*inv, vy*inv, vz*inv);
}

__device__ __forceinline__ float3 o_coord(const float* __restrict__ ca, int i) {
    float3 u  = unitv(ca, i);
    float3 up = unitv(ca, (i > 0) ? i - 1 : 0);
    float3 cai = ldca(ca, i);
    float3 vc = make_float3(0.38f*u.x, 0.38f*u.y, 0.38f*u.z);
    float3 vn = make_float3(-0.38f*up.x, -0.38f*up.y, -0.38f*up.z);
    float px = vc.y*vn.z - vc.z*vn.y;
    float py = vc.z*vn.x - vc.x*vn.z;
    float pz = vc.x*vn.y - vc.y*vn.x;
    float pn = sqrtf(px*px + py*py + pz*pz);
    if (pn > 1e-6f) {
        float inv = 1.0f / fmaxf(pn, 1e-12f);
        px *= inv; py *= inv; pz *= inv;
    }
    return make_float3(cai.x + vc.x + 1.24f*px,
                       cai.y + vc.y + 1.24f*py,
                       cai.z + vc.z + 1.24f*pz);
}

__device__ __forceinline__ float3 n_coord(const float* __restrict__ ca, int j) {
    float3 u = unitv(ca, j - 1);
    float3 caj = ldca(ca, j);
    return make_float3(caj.x - 0.38f*u.x, caj.y - 0.38f*u.y, caj.z - 0.38f*u.z);
}

__global__ void __launch_bounds__(NTHREADS, 8)
energy_kernel(const float* __restrict__ ca, const float* __restrict__ K,
              const int2* __restrict__ pairs, float* __restrict__ out)
{
    __shared__ double sh[NTHREADS / 32];
    __shared__ float srx[CT_ROWS], sry[CT_ROWS], srz[CT_ROWS];
    const int bid = blockIdx.x;
    const int tid = threadIdx.x;

    float acc = 0.0f;
    int role;

    if (bid >= SP_BLOCKS) {
        // ------ contact: software-pipelined K stream (prefetch distance 1) ------
        role = 2;
        const int cb = bid - SP_BLOCKS;
        const int jb = cb & (CT_JBLOCKS - 1);
        const int rb = cb >> 2;                  // log2(CT_JBLOCKS)
        const int j0 = jb * (NTHREADS * 4) + tid * 4;
        const int i0 = rb * CT_ROWS;

        // stage row coords in smem (off the critical path)
        if (tid < CT_ROWS) {
            srx[tid] = __ldg(ca + 3*(i0 + tid) + 0);
            sry[tid] = __ldg(ca + 3*(i0 + tid) + 1);
            srz[tid] = __ldg(ca + 3*(i0 + tid) + 2);
        }

        // column coords in registers
        const float4* cj4 = (const float4*)(ca + 3 * j0);  // 16B-aligned (j0 % 4 == 0)
        float4 A = __ldg(cj4 + 0);
        float4 B = __ldg(cj4 + 1);
        float4 C = __ldg(cj4 + 2);
        const float xj0 = A.x, yj0 = A.y, zj0 = A.z;
        const float xj1 = A.w, yj1 = B.x, zj1 = B.y;
        const float xj2 = B.z, yj2 = B.w, zj2 = C.x;
        const float xj3 = C.y, yj3 = C.z, zj3 = C.w;

        __syncthreads();

        const float4* kp = (const float4*)(K + (size_t)i0 * NRES + j0);
        const size_t rowq = NRES / 4;            // float4 row stride

        float4 kc = __ldcs(kp);                  // prologue: row 0 in flight

        #pragma unroll
        for (int r = 0; r < CT_ROWS; ++r) {
            // prefetch next row BEFORE consuming current (clamped: last row reloads itself)
            const int rn = (r + 1 < CT_ROWS) ? (r + 1) : r;
            const float4 kn = __ldcs(kp + (size_t)rn * rowq);

            const float xi = srx[r];
            const float yi = sry[r];
            const float zi = srz[r];

            float dx, dy, dz, q, d, t, df;

            dx = xi - xj0; dy = yi - yj0; dz = zi - zj0;
            q = fmaf(dx, dx, fmaf(dy, dy, dz * dz));
            d = fast_sqrt(fmaxf(q, 1e-12f));
            t = fmaf(-8.0f, kc.x, 8.0f);
            df = d - t; acc = fmaf(df, df, acc);

            dx = xi - xj1; dy = yi - yj1; dz = zi - zj1;
            q = fmaf(dx, dx, fmaf(dy, dy, dz * dz));
            d = fast_sqrt(fmaxf(q, 1e-12f));
            t = fmaf(-8.0f, kc.y, 8.0f);
            df = d - t; acc = fmaf(df, df, acc);

            dx = xi - xj2; dy = yi - yj2; dz = zi - zj2;
            q = fmaf(dx, dx, fmaf(dy, dy, dz * dz));
            d = fast_sqrt(fmaxf(q, 1e-12f));
            t = fmaf(-8.0f, kc.z, 8.0f);
            df = d - t; acc = fmaf(df, df, acc);

            dx = xi - xj3; dy = yi - yj3; dz = zi - zj3;
            q = fmaf(dx, dx, fmaf(dy, dy, dz * dz));
            d = fast_sqrt(fmaxf(q, 1e-12f));
            t = fmaf(-8.0f, kc.w, 8.0f);
            df = d - t; acc = fmaf(df, df, acc);

            kc = kn;
        }
    } else if (bid < HB_BLOCKS) {
        // ---------------- hydrogen bonds: 16384 items, exactly 1 per thread ----
        role = 3;
        const int idx = bid * NTHREADS + tid;         // [0, 4*NRES)
        const int off = 2 + (idx >> 12);
        const int i = idx & (NRES - 1);
        if (i < NRES - off) {
            const float3 o  = o_coord(ca, i);
            const float3 nc = n_coord(ca, i + off);
            const float dx = o.x - nc.x, dy = o.y - nc.y, dz = o.z - nc.z;
            const float d = sqrtf(dx*dx + dy*dy + dz*dz);
            if (d > 2.5f && d < 3.5f) {
                const float z = (d - 2.95f) * (1.0f / 0.3f);
                acc += expf(-z * z);   // pen; sign/weight applied at finalize
            }
        }
    } else if (bid < HB_BLOCKS + CL_BLOCKS) {
        // ---------------- clash: 500K pairs over 64 blocks -----------------
        role = 1;
        const int b = bid - HB_BLOCKS;
        for (int p = b * NTHREADS + tid; p < NPAIRS; p += CL_BLOCKS * NTHREADS) {
            const int2 pr = __ldg(pairs + p);
            const int i = pr.x, j = pr.y;
            const float dx = __ldg(ca + 3*i + 0) - __ldg(ca + 3*j + 0);
            const float dy = __ldg(ca + 3*i + 1) - __ldg(ca + 3*j + 1);
            const float dz = __ldg(ca + 3*i + 2) - __ldg(ca + 3*j + 2);
            float q = fmaf(dx, dx, fmaf(dy, dy, dz * dz));
            float d = fast_sqrt(fmaxf(q, 1e-12f));
            float r = fmaxf(3.2f - d, 0.0f);
            acc = fmaf(r, r, acc);
        }
    } else {
        // ---------------- bond: 4095 terms -----------------
        role = 0;
        for (int i = tid; i < NRES - 1; i += NTHREADS) {
            const float dx = __ldg(ca + 3*i + 3) - __ldg(ca + 3*i + 0);
            const float dy = __ldg(ca + 3*i + 4) - __ldg(ca + 3*i + 1);
            const float dz = __ldg(ca + 3*i + 5) - __ldg(ca + 3*i + 2);
            const float d = fast_sqrt(fmaf(dx, dx, fmaf(dy, dy, dz * dz)));
            const float df = d - 3.8f;
            acc = fmaf(df, df, acc);
        }
    }

    // ---------------- block reduce (f64) + single atomic ----------------
    double v = (double)acc;
    #pragma unroll
    for (int o = 16; o > 0; o >>= 1) v += __shfl_xor_sync(0xffffffffu, v, o);
    const int lane = tid & 31, w = tid >> 5;
    if (lane == 0) sh[w] = v;
    __syncthreads();

    if (tid == 0) {
        double tot = 0.0;
        #pragma unroll
        for (int i = 0; i < NTHREADS / 32; ++i) tot += sh[i];
        atomicAdd(&g_acc[role], tot);
        __threadfence();
        const unsigned int ticket = atomicAdd(&g_done, 1u);
        if (ticket == (unsigned int)(gridDim.x - 1)) {
            // last block: finalize, write output, self-reset for next graph replay
            const double bond    = atomicAdd(&g_acc[0], 0.0);
            const double clash   = atomicAdd(&g_acc[1], 0.0);
            const double contact = atomicAdd(&g_acc[2], 0.0);
            const double hb      = atomicAdd(&g_acc[3], 0.0);
            const double inv_nn  = 1.0 / ((double)NRES * (double)NRES);
            const double e = 30.0 * bond / (double)(NRES - 1)
                           + 50.0 * clash / (double)NPAIRS
                           + 5.0 * contact * inv_nn
                           - 2.0 * hb * inv_nn;       // 4 * (-0.5*sum) / n^2
            out[0] = (float)e;
            g_acc[0] = 0.0; g_acc[1] = 0.0; g_acc[2] = 0.0; g_acc[3] = 0.0;
            __threadfence();
            g_done = 0u;
        }
    }
}

extern "C" void kernel_launch(void* const* d_in, const int* in_sizes, int n_in,
                              void* d_out, int out_size) {
    const float* ca    = (const float*)d_in[0];
    const float* K     = (const float*)d_in[1];
    const int2*  pairs = (const int2*)d_in[2];
    energy_kernel<<<NB_TOTAL, NTHREADS>>>(ca, K, pairs, (float*)d_out);
}

// round 11
// speedup vs baseline: 2.7024x; 1.4562x over previous
#include <cuda_runtime.h>
#include <cstdint>

#define NRES    4096
#define NPAIRS  500000

#define NTHREADS     256
#define HB_BLOCKS    64                   // 64*256 = 16384 = 4*4096 hb items, 1/thread
#define CL_BLOCKS    64
#define BD_BLOCKS    1
#define SP_BLOCKS    (HB_BLOCKS + CL_BLOCKS + BD_BLOCKS)   // specials first: 129

#define CT_JBLOCKS   4                    // 4096 cols / (256 thr * 4 cols)
#define CT_ROWS      16                   // rows per contact block
#define CT_RBLOCKS   (NRES / CT_ROWS)     // 256
#define CT_BLOCKS    (CT_JBLOCKS * CT_RBLOCKS)  // 1024
#define NB_TOTAL     (SP_BLOCKS + CT_BLOCKS)    // 1153  (< 148*8 = 1184: one wave)

#define STAGES       4                    // bulk-copy ring stages (4 KB each)
#define SEG_BYTES    4096                 // 1024 floats per row segment

// accumulators: [0]=bond, [1]=clash, [2]=contact, [3]=hb pen sum
__device__ double g_acc[4];
__device__ unsigned int g_done;

__device__ __forceinline__ float fast_sqrt(float x) {
    float r; asm("sqrt.approx.f32 %0, %1;" : "=f"(r) : "f"(x)); return r;
}

__device__ __forceinline__ void mbar_init(uint32_t mbar, uint32_t count) {
    asm volatile("mbarrier.init.shared.b64 [%0], %1;" :: "r"(mbar), "r"(count) : "memory");
}
__device__ __forceinline__ void mbar_expect_tx(uint32_t mbar, uint32_t bytes) {
    asm volatile("mbarrier.arrive.expect_tx.shared.b64 _, [%0], %1;"
                 :: "r"(mbar), "r"(bytes) : "memory");
}
__device__ __forceinline__ void bulk_g2s(uint32_t sdst, const void* gsrc, uint32_t bytes,
                                         uint32_t mbar) {
    asm volatile("cp.async.bulk.shared::cta.global.mbarrier::complete_tx::bytes "
                 "[%0], [%1], %2, [%3];"
                 :: "r"(sdst), "l"(gsrc), "r"(bytes), "r"(mbar) : "memory");
}
__device__ __forceinline__ void mbar_wait(uint32_t mbar, uint32_t parity) {
    asm volatile(
        "{\n\t.reg .pred P;\n\t"
        "WAIT_%=:\n\t"
        "mbarrier.try_wait.parity.acquire.cta.shared::cta.b64 P, [%0], %1, 0x989680;\n\t"
        "@!P bra WAIT_%=;\n\t}"
        :: "r"(mbar), "r"(parity) : "memory");
}

__device__ __forceinline__ float3 ldca(const float* __restrict__ ca, int i) {
    return make_float3(__ldg(ca + 3*i), __ldg(ca + 3*i + 1), __ldg(ca + 3*i + 2));
}

__device__ __forceinline__ float3 unitv(const float* __restrict__ ca, int i) {
    float3 a = ldca(ca, i), b = ldca(ca, i + 1);
    float vx = b.x - a.x, vy = b.y - a.y, vz = b.z - a.z;
    float n = sqrtf(vx*vx + vy*vy + vz*vz) + 1e-8f;
    float inv = 1.0f / n;
    return make_float3(vx*inv, vy*inv, vz*inv);
}

__device__ __forceinline__ float3 o_coord(const float* __restrict__ ca, int i) {
    float3 u  = unitv(ca, i);
    float3 up = unitv(ca, (i > 0) ? i - 1 : 0);
    float3 cai = ldca(ca, i);
    float3 vc = make_float3(0.38f*u.x, 0.38f*u.y, 0.38f*u.z);
    float3 vn = make_float3(-0.38f*up.x, -0.38f*up.y, -0.38f*up.z);
    float px = vc.y*vn.z - vc.z*vn.y;
    float py = vc.z*vn.x - vc.x*vn.z;
    float pz = vc.x*vn.y - vc.y*vn.x;
    float pn = sqrtf(px*px + py*py + pz*pz);
    if (pn > 1e-6f) {
        float inv = 1.0f / fmaxf(pn, 1e-12f);
        px *= inv; py *= inv; pz *= inv;
    }
    return make_float3(cai.x + vc.x + 1.24f*px,
                       cai.y + vc.y + 1.24f*py,
                       cai.z + vc.z + 1.24f*pz);
}

__device__ __forceinline__ float3 n_coord(const float* __restrict__ ca, int j) {
    float3 u = unitv(ca, j - 1);
    float3 caj = ldca(ca, j);
    return make_float3(caj.x - 0.38f*u.x, caj.y - 0.38f*u.y, caj.z - 0.38f*u.z);
}

__global__ void __launch_bounds__(NTHREADS, 8)
energy_kernel(const float* __restrict__ ca, const float* __restrict__ K,
              const int2* __restrict__ pairs, float* __restrict__ out)
{
    __shared__ double sh[NTHREADS / 32];
    __shared__ __align__(128) float kstage[STAGES][SEG_BYTES / 4];  // 16 KB ring
    __shared__ __align__(8) uint64_t mbar[STAGES];
    const int bid = blockIdx.x;
    const int tid = threadIdx.x;

    float acc = 0.0f;
    int role;

    if (bid >= SP_BLOCKS) {
        // ---- contact: K streamed via cp.async.bulk (TMA path) into smem ----
        role = 2;
        const int cb = bid - SP_BLOCKS;
        const int jb = cb & (CT_JBLOCKS - 1);
        const int rb = cb >> 2;                  // log2(CT_JBLOCKS)
        const int j0 = jb * (NTHREADS * 4) + tid * 4;
        const int i0 = rb * CT_ROWS;

        // column coords in registers
        const float4* cj4 = (const float4*)(ca + 3 * j0);  // 16B-aligned (j0 % 4 == 0)
        float4 A = __ldg(cj4 + 0);
        float4 B = __ldg(cj4 + 1);
        float4 C = __ldg(cj4 + 2);
        const float xj0 = A.x, yj0 = A.y, zj0 = A.z;
        const float xj1 = A.w, yj1 = B.x, zj1 = B.y;
        const float xj2 = B.z, yj2 = B.w, zj2 = C.x;
        const float xj3 = C.y, yj3 = C.z, zj3 = C.w;

        uint32_t mb[STAGES], sb[STAGES];
        #pragma unroll
        for (int s = 0; s < STAGES; ++s) {
            mb[s] = (uint32_t)__cvta_generic_to_shared(&mbar[s]);
            sb[s] = (uint32_t)__cvta_generic_to_shared(&kstage[s][0]);
        }
        if (tid == 0) {
            #pragma unroll
            for (int s = 0; s < STAGES; ++s) mbar_init(mb[s], 1);
        }
        __syncthreads();

        const char* gbase = (const char*)K
                          + (size_t)i0 * (NRES * 4) + (size_t)jb * SEG_BYTES;

        #pragma unroll
        for (int c = 0; c < CT_ROWS / STAGES; ++c) {
            if (tid == 0) {
                #pragma unroll
                for (int s = 0; s < STAGES; ++s) {
                    mbar_expect_tx(mb[s], SEG_BYTES);
                    bulk_g2s(sb[s], gbase + (size_t)(c * STAGES + s) * (NRES * 4),
                             SEG_BYTES, mb[s]);
                }
            }
            #pragma unroll
            for (int s = 0; s < STAGES; ++s) {
                mbar_wait(mb[s], c & 1);
                const float4 k = *(const float4*)&kstage[s][tid * 4];
                const int i = i0 + c * STAGES + s;
                const float xi = __ldg(ca + 3*i + 0);
                const float yi = __ldg(ca + 3*i + 1);
                const float zi = __ldg(ca + 3*i + 2);

                float dx, dy, dz, q, d, t, df;

                dx = xi - xj0; dy = yi - yj0; dz = zi - zj0;
                q = fmaf(dx, dx, fmaf(dy, dy, dz * dz));
                d = fast_sqrt(fmaxf(q, 1e-12f));
                t = fmaf(-8.0f, k.x, 8.0f);
                df = d - t; acc = fmaf(df, df, acc);

                dx = xi - xj1; dy = yi - yj1; dz = zi - zj1;
                q = fmaf(dx, dx, fmaf(dy, dy, dz * dz));
                d = fast_sqrt(fmaxf(q, 1e-12f));
                t = fmaf(-8.0f, k.y, 8.0f);
                df = d - t; acc = fmaf(df, df, acc);

                dx = xi - xj2; dy = yi - yj2; dz = zi - zj2;
                q = fmaf(dx, dx, fmaf(dy, dy, dz * dz));
                d = fast_sqrt(fmaxf(q, 1e-12f));
                t = fmaf(-8.0f, k.z, 8.0f);
                df = d - t; acc = fmaf(df, df, acc);

                dx = xi - xj3; dy = yi - yj3; dz = zi - zj3;
                q = fmaf(dx, dx, fmaf(dy, dy, dz * dz));
                d = fast_sqrt(fmaxf(q, 1e-12f));
                t = fmaf(-8.0f, k.w, 8.0f);
                df = d - t; acc = fmaf(df, df, acc);
            }
            __syncthreads();   // all consumed before stages are reused
        }
    } else if (bid < HB_BLOCKS) {
        // ---------------- hydrogen bonds: 16384 items, exactly 1 per thread ----
        role = 3;
        const int idx = bid * NTHREADS + tid;         // [0, 4*NRES)
        const int off = 2 + (idx >> 12);
        const int i = idx & (NRES - 1);
        if (i < NRES - off) {
            const float3 o  = o_coord(ca, i);
            const float3 nc = n_coord(ca, i + off);
            const float dx = o.x - nc.x, dy = o.y - nc.y, dz = o.z - nc.z;
            const float d = sqrtf(dx*dx + dy*dy + dz*dz);
            if (d > 2.5f && d < 3.5f) {
                const float z = (d - 2.95f) * (1.0f / 0.3f);
                acc += expf(-z * z);   // pen; sign/weight applied at finalize
            }
        }
    } else if (bid < HB_BLOCKS + CL_BLOCKS) {
        // ---------------- clash: 500K pairs over 64 blocks -----------------
        role = 1;
        const int b = bid - HB_BLOCKS;
        for (int p = b * NTHREADS + tid; p < NPAIRS; p += CL_BLOCKS * NTHREADS) {
            const int2 pr = __ldg(pairs + p);
            const int i = pr.x, j = pr.y;
            const float dx = __ldg(ca + 3*i + 0) - __ldg(ca + 3*j + 0);
            const float dy = __ldg(ca + 3*i + 1) - __ldg(ca + 3*j + 1);
            const float dz = __ldg(ca + 3*i + 2) - __ldg(ca + 3*j + 2);
            float q = fmaf(dx, dx, fmaf(dy, dy, dz * dz));
            float d = fast_sqrt(fmaxf(q, 1e-12f));
            float r = fmaxf(3.2f - d, 0.0f);
            acc = fmaf(r, r, acc);
        }
    } else {
        // ---------------- bond: 4095 terms -----------------
        role = 0;
        for (int i = tid; i < NRES - 1; i += NTHREADS) {
            const float dx = __ldg(ca + 3*i + 3) - __ldg(ca + 3*i + 0);
            const float dy = __ldg(ca + 3*i + 4) - __ldg(ca + 3*i + 1);
            const float dz = __ldg(ca + 3*i + 5) - __ldg(ca + 3*i + 2);
            const float d = fast_sqrt(fmaf(dx, dx, fmaf(dy, dy, dz * dz)));
            const float df = d - 3.8f;
            acc = fmaf(df, df, acc);
        }
    }

    // ---------------- block reduce (f64) + single atomic ----------------
    double v = (double)acc;
    #pragma unroll
    for (int o = 16; o > 0; o >>= 1) v += __shfl_xor_sync(0xffffffffu, v, o);
    const int lane = tid & 31, w = tid >> 5;
    if (lane == 0) sh[w] = v;
    __syncthreads();

    if (tid == 0) {
        double tot = 0.0;
        #pragma unroll
        for (int i = 0; i < NTHREADS / 32; ++i) tot += sh[i];
        atomicAdd(&g_acc[role], tot);
        __threadfence();
        const unsigned int ticket = atomicAdd(&g_done, 1u);
        if (ticket == (unsigned int)(gridDim.x - 1)) {
            // last block: finalize, write output, self-reset for next graph replay
            const double bond    = atomicAdd(&g_acc[0], 0.0);
            const double clash   = atomicAdd(&g_acc[1], 0.0);
            const double contact = atomicAdd(&g_acc[2], 0.0);
            const double hb      = atomicAdd(&g_acc[3], 0.0);
            const double inv_nn  = 1.0 / ((double)NRES * (double)NRES);
            const double e = 30.0 * bond / (double)(NRES - 1)
                           + 50.0 * clash / (double)NPAIRS
                           + 5.0 * contact * inv_nn
                           - 2.0 * hb * inv_nn;       // 4 * (-0.5*sum) / n^2
            out[0] = (float)e;
            g_acc[0] = 0.0; g_acc[1] = 0.0; g_acc[2] = 0.0; g_acc[3] = 0.0;
            __threadfence();
            g_done = 0u;
        }
    }
}

extern "C" void kernel_launch(void* const* d_in, const int* in_sizes, int n_in,
                              void* d_out, int out_size) {
    const float* ca    = (const float*)d_in[0];
    const float* K     = (const float*)d_in[1];
    const int2*  pairs = (const int2*)d_in[2];
    energy_kernel<<<NB_TOTAL, NTHREADS>>>(ca, K, pairs, (float*)d_out);
}